// round 6
// baseline (speedup 1.0000x reference)
#include <cuda_runtime.h>
#include <math.h>
#include <stdint.h>

// Problem constants
#define D_MODEL 1024
#define NH      16
#define DK_     64
#define MROWS   4096      // B*L = 2*2048
#define DFF_    4096
#define SEQL    2048

// ---------------------------------------------------------------------------
// Scratch (static device globals; no allocations allowed)
// ---------------------------------------------------------------------------
__device__ float g_q   [MROWS * D_MODEL];
__device__ float g_k   [MROWS * D_MODEL];
__device__ float g_v   [MROWS * D_MODEL];
__device__ float g_ctx [MROWS * D_MODEL];
__device__ float g_proj[MROWS * D_MODEL];
__device__ float g_x1  [MROWS * D_MODEL];
__device__ float g_x2  [MROWS * D_MODEL];
__device__ float g_ff  [MROWS * DFF_];
// tf32-RNA pre-rounded GEMM operands
__device__ float g_wr  [16 * 1024 * 1024];   // weights: 8x1M proj + 4M ff1 + 4M ff2
__device__ float g_xr  [MROWS * D_MODEL];    // rounded x
__device__ float g_er  [MROWS * D_MODEL];    // rounded encoder_output
__device__ float g_x1r [MROWS * D_MODEL];    // rounded x1
__device__ float g_x2r [MROWS * D_MODEL];    // rounded x2

__device__ __forceinline__ float gelu_exact(float x) {
    return 0.5f * x * (1.0f + erff(x * 0.70710678118654752f));
}

__device__ __forceinline__ float to_tf32(float x) {
    uint32_t u;
    asm volatile("cvt.rna.tf32.f32 %0, %1;" : "=r"(u) : "f"(x));
    return __uint_as_float(u);
}
__device__ __forceinline__ uint32_t to_tf32_bits(float x) {
    uint32_t u;
    asm volatile("cvt.rna.tf32.f32 %0, %1;" : "=r"(u) : "f"(x));
    return u;
}

__device__ __forceinline__ void mma_tf32(float* c, const uint32_t* a, const uint32_t* b) {
    asm volatile(
        "mma.sync.aligned.m16n8k8.row.col.f32.tf32.tf32.f32 "
        "{%0,%1,%2,%3}, {%4,%5,%6,%7}, {%8,%9}, {%0,%1,%2,%3};\n"
        : "+f"(c[0]), "+f"(c[1]), "+f"(c[2]), "+f"(c[3])
        : "r"(a[0]), "r"(a[1]), "r"(a[2]), "r"(a[3]), "r"(b[0]), "r"(b[1]));
}

// cp.async helpers
__device__ __forceinline__ void cp_async16(void* smem, const void* gmem) {
    uint32_t s = (uint32_t)__cvta_generic_to_shared(smem);
    asm volatile("cp.async.cg.shared.global [%0], [%1], 16;\n" :: "r"(s), "l"(gmem));
}
__device__ __forceinline__ void cp_commit() {
    asm volatile("cp.async.commit_group;\n" ::: "memory");
}
template<int N>
__device__ __forceinline__ void cp_wait() {
    asm volatile("cp.async.wait_group %0;\n" :: "n"(N) : "memory");
}

// ---------------------------------------------------------------------------
// Elementwise tf32-RNA rounding (grid-stride, float4)
// ---------------------------------------------------------------------------
__global__ __launch_bounds__(256)
void round_tf32(const float* __restrict__ in, float* __restrict__ out, int n4)
{
    const int i = blockIdx.x * 256 + threadIdx.x;
    const int stride = gridDim.x * 256;
    for (int idx = i; idx < n4; idx += stride) {
        float4 v = ((const float4*)in)[idx];
        v.x = to_tf32(v.x); v.y = to_tf32(v.y);
        v.z = to_tf32(v.z); v.w = to_tf32(v.w);
        ((float4*)out)[idx] = v;
    }
}

// ---------------------------------------------------------------------------
// TF32 tensor-core GEMM, cp.async 3-stage, GBK=16, one barrier per k-tile.
// Inputs are PRE-ROUNDED to tf32 (RNA); no cvt in the hot loop.
// C[M,N] = A[M,K] @ B[K,N] + bias, ACT 0=none 1=gelu(+tf32-round output)
// CTA tile 128x128, 8 warps (2x4), warp tile 64x32.
// ---------------------------------------------------------------------------
#define GBM 128
#define GBN 128
#define GBK 16
#define APAD 20
#define BPAD 136
#define STAGES 3

template<int ACT>
__global__ __launch_bounds__(256, 2)
void gemm_tf32(const float* __restrict__ A, const float* __restrict__ B,
               const float* __restrict__ bias, float* __restrict__ C,
               int M, int N, int K)
{
    __shared__ float As[STAGES][GBM][APAD];   // 30720 B
    __shared__ float Bs[STAGES][GBK][BPAD];   // 26112 B

    const int t    = threadIdx.x;
    const int wid  = t >> 5;
    const int lane = t & 31;
    const int wm   = wid >> 2;        // 0..1
    const int wn   = wid & 3;         // 0..3
    const int lr   = lane >> 2;       // 0..7
    const int lc   = lane & 3;        // 0..3

    const int m0 = blockIdx.y * GBM;
    const int n0 = blockIdx.x * GBN;

    // cp.async mapping (2 x 16B chunks per thread per matrix):
    const int arow = t >> 1;          // 0..127
    const int acol = (t & 1) * 4;     // 0 or 4 (second chunk +8)
    const int brow = t >> 4;          // 0..15
    const int bcol = (t & 15) * 8;    // 0..120 (second chunk +4)

    const float* Ag = A + (size_t)(m0 + arow) * K + acol;
    const float* Bg = B + (size_t)brow * N + n0 + bcol;

    float acc[4][4][4];
#pragma unroll
    for (int i = 0; i < 4; i++)
#pragma unroll
        for (int j = 0; j < 4; j++)
#pragma unroll
            for (int r = 0; r < 4; r++) acc[i][j][r] = 0.0f;

    const int kTiles = K / GBK;

    // Prologue: stages 0 and 1 in flight
#pragma unroll
    for (int s = 0; s < 2; s++) {
        const size_t ko = (size_t)s * GBK;
        cp_async16(&As[s][arow][acol],     Ag + ko);
        cp_async16(&As[s][arow][acol + 8], Ag + ko + 8);
        cp_async16(&Bs[s][brow][bcol],     Bg + ko * N);
        cp_async16(&Bs[s][brow][bcol + 4], Bg + ko * N + 4);
        cp_commit();
    }

    int p = 0;
    for (int kt = 0; kt < kTiles; kt++) {
        cp_wait<1>();          // stage kt complete (one younger group may pend)
        __syncthreads();       // everyone past compute of stage (p+2)%3's prior life

        // Issue stage kt+2 into (p+2)%3 — safe: all warps finished computing it
        if (kt + 2 < kTiles) {
            const int s = (p + 2) % STAGES;
            const size_t ko = (size_t)(kt + 2) * GBK;
            cp_async16(&As[s][arow][acol],     Ag + ko);
            cp_async16(&As[s][arow][acol + 8], Ag + ko + 8);
            cp_async16(&Bs[s][brow][bcol],     Bg + ko * N);
            cp_async16(&Bs[s][brow][bcol + 4], Bg + ko * N + 4);
        }
        cp_commit();

        // ---- compute stage p: two K=8 steps ----
#pragma unroll
        for (int ks = 0; ks < 2; ks++) {
            const int kk = ks * 8;
            uint32_t afr[4][4];
            uint32_t bfr[4][2];
#pragma unroll
            for (int mf = 0; mf < 4; mf++) {
                const int m = wm * 64 + mf * 16 + lr;
                afr[mf][0] = __float_as_uint(As[p][m    ][kk + lc]);
                afr[mf][1] = __float_as_uint(As[p][m + 8][kk + lc]);
                afr[mf][2] = __float_as_uint(As[p][m    ][kk + lc + 4]);
                afr[mf][3] = __float_as_uint(As[p][m + 8][kk + lc + 4]);
            }
#pragma unroll
            for (int nf = 0; nf < 4; nf++) {
                const int n = wn * 32 + nf * 8 + lr;
                bfr[nf][0] = __float_as_uint(Bs[p][kk + lc    ][n]);
                bfr[nf][1] = __float_as_uint(Bs[p][kk + lc + 4][n]);
            }
#pragma unroll
            for (int mf = 0; mf < 4; mf++)
#pragma unroll
                for (int nf = 0; nf < 4; nf++)
                    mma_tf32(acc[mf][nf], afr[mf], bfr[nf]);
        }

        p = (p + 1) % STAGES;
    }

    // Epilogue
#pragma unroll
    for (int mf = 0; mf < 4; mf++) {
        const int r0 = m0 + wm * 64 + mf * 16 + lr;
#pragma unroll
        for (int nf = 0; nf < 4; nf++) {
            const int c0 = n0 + wn * 32 + nf * 8 + 2 * lc;
            const float b0 = bias[c0], b1 = bias[c0 + 1];
            float v0 = acc[mf][nf][0] + b0;
            float v1 = acc[mf][nf][1] + b1;
            float v2 = acc[mf][nf][2] + b0;
            float v3 = acc[mf][nf][3] + b1;
            if (ACT == 1) {   // gelu, then round for the downstream GEMM
                v0 = to_tf32(gelu_exact(v0)); v1 = to_tf32(gelu_exact(v1));
                v2 = to_tf32(gelu_exact(v2)); v3 = to_tf32(gelu_exact(v3));
            }
            *(float2*)(C + (size_t)r0 * N + c0)       = make_float2(v0, v1);
            *(float2*)(C + (size_t)(r0 + 8) * N + c0) = make_float2(v2, v3);
        }
    }
}

// ---------------------------------------------------------------------------
// Tensor-core flash attention (TF32 mma), DK=64 — round-3 structure,
// epilogue writes tf32-rounded output (sole consumer is the O-proj GEMM).
// ---------------------------------------------------------------------------
#define KS_STRIDE 68
#define VS_STRIDE 72

template<bool CAUSAL>
__global__ __launch_bounds__(256)
void flash_attn_tc(const float* __restrict__ Q, const float* __restrict__ K,
                   const float* __restrict__ V, float* __restrict__ O, int L)
{
    __shared__ float Ks[64][KS_STRIDE];
    __shared__ float Vs[64][VS_STRIDE];

    const int t    = threadIdx.x;
    const int lane = t & 31;
    const int w    = t >> 5;
    const int lr   = lane >> 2;
    const int lc   = lane & 3;

    const int qt = blockIdx.x;
    const int bh = blockIdx.y;
    const int b  = bh >> 4;
    const int h  = bh & 15;
    const int q0 = qt * 128;
    const int wrow = q0 + w * 16;

    const float* Qb = Q + (size_t)(b * L) * D_MODEL + h * DK_;
    const float* Kb = K + (size_t)(b * L) * D_MODEL + h * DK_;
    const float* Vb = V + (size_t)(b * L) * D_MODEL + h * DK_;

    uint32_t qf[8][4];
    {
        const float* qr0 = Qb + (size_t)(wrow + lr) * D_MODEL;
        const float* qr1 = Qb + (size_t)(wrow + lr + 8) * D_MODEL;
#pragma unroll
        for (int kc = 0; kc < 8; kc++) {
            qf[kc][0] = to_tf32_bits(0.125f * qr0[8 * kc + lc]);
            qf[kc][1] = to_tf32_bits(0.125f * qr1[8 * kc + lc]);
            qf[kc][2] = to_tf32_bits(0.125f * qr0[8 * kc + lc + 4]);
            qf[kc][3] = to_tf32_bits(0.125f * qr1[8 * kc + lc + 4]);
        }
    }

    float o[8][4];
#pragma unroll
    for (int nf = 0; nf < 8; nf++)
#pragma unroll
        for (int i = 0; i < 4; i++) o[nf][i] = 0.0f;
    float m0r = -1e30f, m1r = -1e30f;
    float l0r = 0.0f,  l1r = 0.0f;

    const int ntile = CAUSAL ? (2 * qt + 2) : (L >> 6);

    for (int kt = 0; kt < ntile; kt++) {
        const int k0 = kt * 64;
        __syncthreads();
#pragma unroll
        for (int i = 0; i < 4; i++) {
            const int idx = i * 256 + t;
            const int row = idx >> 4;
            const int c4  = (idx & 15) * 4;
            const size_t g = (size_t)(k0 + row) * D_MODEL + c4;
            float4 kv = *(const float4*)(Kb + g);
            float4 vv = *(const float4*)(Vb + g);
            float4 s;
            s.x = to_tf32(kv.x); s.y = to_tf32(kv.y); s.z = to_tf32(kv.z); s.w = to_tf32(kv.w);
            *(float4*)&Ks[row][c4] = s;
            s.x = to_tf32(vv.x); s.y = to_tf32(vv.y); s.z = to_tf32(vv.z); s.w = to_tf32(vv.w);
            *(float4*)&Vs[row][c4] = s;
        }
        __syncthreads();

        const bool active = (!CAUSAL) || (k0 <= wrow + 15);
        if (active) {
            float sacc[8][4];
#pragma unroll
            for (int nf = 0; nf < 8; nf++) {
                sacc[nf][0] = sacc[nf][1] = sacc[nf][2] = sacc[nf][3] = 0.0f;
#pragma unroll
                for (int kc = 0; kc < 8; kc++) {
                    uint32_t bfr[2];
                    bfr[0] = __float_as_uint(Ks[8 * nf + lr][8 * kc + lc]);
                    bfr[1] = __float_as_uint(Ks[8 * nf + lr][8 * kc + lc + 4]);
                    mma_tf32(sacc[nf], qf[kc], bfr);
                }
            }

            if (CAUSAL && (k0 + 63 > wrow)) {
                const int r0 = wrow + lr, r1 = wrow + lr + 8;
#pragma unroll
                for (int nf = 0; nf < 8; nf++) {
                    const int key = k0 + 8 * nf + 2 * lc;
                    if (key     > r0) sacc[nf][0] = -1e30f;
                    if (key + 1 > r0) sacc[nf][1] = -1e30f;
                    if (key     > r1) sacc[nf][2] = -1e30f;
                    if (key + 1 > r1) sacc[nf][3] = -1e30f;
                }
            }

            float mx0 = -1e30f, mx1 = -1e30f;
#pragma unroll
            for (int nf = 0; nf < 8; nf++) {
                mx0 = fmaxf(mx0, fmaxf(sacc[nf][0], sacc[nf][1]));
                mx1 = fmaxf(mx1, fmaxf(sacc[nf][2], sacc[nf][3]));
            }
            mx0 = fmaxf(mx0, __shfl_xor_sync(0xffffffffu, mx0, 1));
            mx0 = fmaxf(mx0, __shfl_xor_sync(0xffffffffu, mx0, 2));
            mx1 = fmaxf(mx1, __shfl_xor_sync(0xffffffffu, mx1, 1));
            mx1 = fmaxf(mx1, __shfl_xor_sync(0xffffffffu, mx1, 2));

            const float nm0 = fmaxf(m0r, mx0);
            const float nm1 = fmaxf(m1r, mx1);
            const float cr0 = __expf(m0r - nm0);
            const float cr1 = __expf(m1r - nm1);
            float sum0 = 0.f, sum1 = 0.f;
#pragma unroll
            for (int nf = 0; nf < 8; nf++) {
                sacc[nf][0] = __expf(sacc[nf][0] - nm0);
                sacc[nf][1] = __expf(sacc[nf][1] - nm0);
                sacc[nf][2] = __expf(sacc[nf][2] - nm1);
                sacc[nf][3] = __expf(sacc[nf][3] - nm1);
                sum0 += sacc[nf][0] + sacc[nf][1];
                sum1 += sacc[nf][2] + sacc[nf][3];
            }
            sum0 += __shfl_xor_sync(0xffffffffu, sum0, 1);
            sum0 += __shfl_xor_sync(0xffffffffu, sum0, 2);
            sum1 += __shfl_xor_sync(0xffffffffu, sum1, 1);
            sum1 += __shfl_xor_sync(0xffffffffu, sum1, 2);

            l0r = l0r * cr0 + sum0;
            l1r = l1r * cr1 + sum1;
            m0r = nm0; m1r = nm1;
#pragma unroll
            for (int nf = 0; nf < 8; nf++) {
                o[nf][0] *= cr0; o[nf][1] *= cr0;
                o[nf][2] *= cr1; o[nf][3] *= cr1;
            }

            const int qbase = lane & ~3;
            const int srcA  = qbase | (lc >> 1);
            const int srcB  = srcA + 2;
#pragma unroll
            for (int kc = 0; kc < 8; kc++) {
                const float p0a = __shfl_sync(0xffffffffu, sacc[kc][0], srcA);
                const float p1a = __shfl_sync(0xffffffffu, sacc[kc][1], srcA);
                const float p2a = __shfl_sync(0xffffffffu, sacc[kc][2], srcA);
                const float p3a = __shfl_sync(0xffffffffu, sacc[kc][3], srcA);
                const float p0b = __shfl_sync(0xffffffffu, sacc[kc][0], srcB);
                const float p1b = __shfl_sync(0xffffffffu, sacc[kc][1], srcB);
                const float p2b = __shfl_sync(0xffffffffu, sacc[kc][2], srcB);
                const float p3b = __shfl_sync(0xffffffffu, sacc[kc][3], srcB);
                uint32_t af[4];
                const bool odd = (lc & 1);
                af[0] = __float_as_uint(odd ? p1a : p0a);
                af[1] = __float_as_uint(odd ? p3a : p2a);
                af[2] = __float_as_uint(odd ? p1b : p0b);
                af[3] = __float_as_uint(odd ? p3b : p2b);
#pragma unroll
                for (int nf = 0; nf < 8; nf++) {
                    uint32_t bfr[2];
                    bfr[0] = __float_as_uint(Vs[8 * kc + lc    ][8 * nf + lr]);
                    bfr[1] = __float_as_uint(Vs[8 * kc + lc + 4][8 * nf + lr]);
                    mma_tf32(o[nf], af, bfr);
                }
            }
        }
    }

    const float inv0 = 1.0f / l0r;
    const float inv1 = 1.0f / l1r;
    float* O0 = O + (size_t)(b * L + wrow + lr) * D_MODEL + h * DK_;
    float* O1 = O + (size_t)(b * L + wrow + lr + 8) * D_MODEL + h * DK_;
#pragma unroll
    for (int nf = 0; nf < 8; nf++) {
        const int c = 8 * nf + 2 * lc;
        *(float2*)(O0 + c) = make_float2(to_tf32(o[nf][0] * inv0), to_tf32(o[nf][1] * inv0));
        *(float2*)(O1 + c) = make_float2(to_tf32(o[nf][2] * inv1), to_tf32(o[nf][3] * inv1));
    }
}

// ---------------------------------------------------------------------------
// Fused residual add + LayerNorm. Optionally writes a second, tf32-rounded
// copy for the downstream GEMM (residual path stays exact).
// ---------------------------------------------------------------------------
template<bool DUAL>
__global__ __launch_bounds__(128)
void add_layernorm(const float* __restrict__ A, const float* __restrict__ Bb,
                   const float* __restrict__ g, const float* __restrict__ be,
                   float* __restrict__ out, float* __restrict__ out_r)
{
    const int row = blockIdx.x;
    const int t = threadIdx.x;
    const float* a = A  + (size_t)row * D_MODEL;
    const float* b = Bb + (size_t)row * D_MODEL;

    float v[8];
    float s = 0.f, sq = 0.f;
#pragma unroll
    for (int i = 0; i < 8; i++) {
        const int c = t + i * 128;
        v[i] = a[c] + b[c];
        s += v[i];
        sq = fmaf(v[i], v[i], sq);
    }
#pragma unroll
    for (int o = 16; o > 0; o >>= 1) {
        s  += __shfl_down_sync(0xffffffffu, s,  o);
        sq += __shfl_down_sync(0xffffffffu, sq, o);
    }
    __shared__ float rs[4], rq[4];
    __shared__ float mean_s, rstd_s;
    const int w = t >> 5, ln = t & 31;
    if (ln == 0) { rs[w] = s; rq[w] = sq; }
    __syncthreads();
    if (t == 0) {
        const float S  = rs[0] + rs[1] + rs[2] + rs[3];
        const float Q2 = rq[0] + rq[1] + rq[2] + rq[3];
        const float mean = S * (1.0f / 1024.0f);
        const float var  = Q2 * (1.0f / 1024.0f) - mean * mean;
        mean_s = mean;
        rstd_s = rsqrtf(var + 1e-5f);
    }
    __syncthreads();
    const float mean = mean_s, rstd = rstd_s;
    float* op = out + (size_t)row * D_MODEL;
    float* orp = DUAL ? out_r + (size_t)row * D_MODEL : nullptr;
#pragma unroll
    for (int i = 0; i < 8; i++) {
        const int c = t + i * 128;
        const float y = (v[i] - mean) * rstd * g[c] + be[c];
        op[c] = y;
        if (DUAL) orp[c] = to_tf32(y);
    }
}

// ---------------------------------------------------------------------------
// Host launcher
// ---------------------------------------------------------------------------
static float* devptr(const void* sym) {
    void* p = nullptr;
    cudaGetSymbolAddress(&p, sym);
    return (float*)p;
}

extern "C" void kernel_launch(void* const* d_in, const int* in_sizes, int n_in,
                              void* d_out, int out_size)
{
    const float* x   = (const float*)d_in[0];
    const float* enc = (const float*)d_in[1];
    const float* swq = (const float*)d_in[4];
    const float* sbq = (const float*)d_in[5];
    const float* swk = (const float*)d_in[6];
    const float* sbk = (const float*)d_in[7];
    const float* swv = (const float*)d_in[8];
    const float* sbv = (const float*)d_in[9];
    const float* swo = (const float*)d_in[10];
    const float* sbo = (const float*)d_in[11];
    const float* cwq = (const float*)d_in[12];
    const float* cbq = (const float*)d_in[13];
    const float* cwk = (const float*)d_in[14];
    const float* cbk = (const float*)d_in[15];
    const float* cwv = (const float*)d_in[16];
    const float* cbv = (const float*)d_in[17];
    const float* cwo = (const float*)d_in[18];
    const float* cbo = (const float*)d_in[19];
    const float* fw1 = (const float*)d_in[20];
    const float* fb1 = (const float*)d_in[21];
    const float* fw2 = (const float*)d_in[22];
    const float* fb2 = (const float*)d_in[23];
    const float* n1g = (const float*)d_in[24];
    const float* n1b = (const float*)d_in[25];
    const float* n2g = (const float*)d_in[26];
    const float* n2b = (const float*)d_in[27];
    const float* n3g = (const float*)d_in[28];
    const float* n3b = (const float*)d_in[29];
    float* out = (float*)d_out;

    float* q    = devptr(g_q);
    float* k    = devptr(g_k);
    float* v    = devptr(g_v);
    float* ctx  = devptr(g_ctx);
    float* proj = devptr(g_proj);
    float* x1   = devptr(g_x1);
    float* x2   = devptr(g_x2);
    float* ff   = devptr(g_ff);
    float* wr   = devptr(g_wr);
    float* xr   = devptr(g_xr);
    float* er   = devptr(g_er);
    float* x1r  = devptr(g_x1r);
    float* x2r  = devptr(g_x2r);

    const int M = MROWS, Dm = D_MODEL, Dff = DFF_;
    const int W1 = Dm * Dm;          // 1M floats per projection weight
    dim3 blk(256);
    dim3 gP (Dm  / GBN, M / GBM);   // (8, 32)
    dim3 gF1(Dff / GBN, M / GBM);   // (32, 32)
    dim3 gA (SEQL / 128, 32);       // (16, B*H)

    // ---- pre-round all GEMM operands (RNA tf32) ----
    round_tf32<<<512, 256>>>(swq, wr + 0 * W1, W1 / 4);
    round_tf32<<<512, 256>>>(swk, wr + 1 * W1, W1 / 4);
    round_tf32<<<512, 256>>>(swv, wr + 2 * W1, W1 / 4);
    round_tf32<<<512, 256>>>(swo, wr + 3 * W1, W1 / 4);
    round_tf32<<<512, 256>>>(cwq, wr + 4 * W1, W1 / 4);
    round_tf32<<<512, 256>>>(cwk, wr + 5 * W1, W1 / 4);
    round_tf32<<<512, 256>>>(cwv, wr + 6 * W1, W1 / 4);
    round_tf32<<<512, 256>>>(cwo, wr + 7 * W1, W1 / 4);
    round_tf32<<<1024, 256>>>(fw1, wr + 8 * W1,  Dm * Dff / 4);
    round_tf32<<<1024, 256>>>(fw2, wr + 12 * W1, Dff * Dm / 4);
    round_tf32<<<1024, 256>>>(x,   xr, M * Dm / 4);
    round_tf32<<<1024, 256>>>(enc, er, M * Dm / 4);

    // ---- self attention ----
    gemm_tf32<0><<<gP, blk>>>(xr, wr + 0 * W1, sbq, q, M, Dm, Dm);
    gemm_tf32<0><<<gP, blk>>>(xr, wr + 1 * W1, sbk, k, M, Dm, Dm);
    gemm_tf32<0><<<gP, blk>>>(xr, wr + 2 * W1, sbv, v, M, Dm, Dm);
    flash_attn_tc<true><<<gA, 256>>>(q, k, v, ctx, SEQL);
    gemm_tf32<0><<<gP, blk>>>(ctx, wr + 3 * W1, sbo, proj, M, Dm, Dm);
    add_layernorm<true><<<M, 128>>>(x, proj, n1g, n1b, x1, x1r);

    // ---- cross attention ----
    gemm_tf32<0><<<gP, blk>>>(x1r, wr + 4 * W1, cbq, q, M, Dm, Dm);
    gemm_tf32<0><<<gP, blk>>>(er,  wr + 5 * W1, cbk, k, M, Dm, Dm);
    gemm_tf32<0><<<gP, blk>>>(er,  wr + 6 * W1, cbv, v, M, Dm, Dm);
    flash_attn_tc<false><<<gA, 256>>>(q, k, v, ctx, SEQL);
    gemm_tf32<0><<<gP, blk>>>(ctx, wr + 7 * W1, cbo, proj, M, Dm, Dm);
    add_layernorm<true><<<M, 128>>>(x1, proj, n2g, n2b, x2, x2r);

    // ---- feed-forward ----
    gemm_tf32<1><<<gF1, blk>>>(x2r, wr + 8 * W1,  fb1, ff, M, Dff, Dm);
    gemm_tf32<0><<<gP,  blk>>>(ff,  wr + 12 * W1, fb2, proj, M, Dm, Dff);
    add_layernorm<false><<<M, 128>>>(x2, proj, n3g, n3b, out, nullptr);
}

// round 7
// speedup vs baseline: 1.0981x; 1.0981x over previous
#include <cuda_runtime.h>
#include <math.h>
#include <stdint.h>

// Problem constants
#define D_MODEL 1024
#define NH      16
#define DK_     64
#define MROWS   4096      // B*L = 2*2048
#define DFF_    4096
#define SEQL    2048

// ---------------------------------------------------------------------------
// Scratch (static device globals; no allocations allowed)
// ---------------------------------------------------------------------------
__device__ float g_q   [MROWS * D_MODEL];
__device__ float g_k   [MROWS * D_MODEL];
__device__ float g_v   [MROWS * D_MODEL];
__device__ float g_ctx [MROWS * D_MODEL];
__device__ float g_proj[MROWS * D_MODEL];
__device__ float g_x1  [MROWS * D_MODEL];
__device__ float g_x2  [MROWS * D_MODEL];
__device__ float g_ff  [MROWS * DFF_];
// tf32-RNA pre-rounded GEMM operands
__device__ float g_wr  [16 * 1024 * 1024];   // 8x1M proj + 4M ff1 + 4M ff2
__device__ float g_xr  [MROWS * D_MODEL];
__device__ float g_er  [MROWS * D_MODEL];
__device__ float g_x1r [MROWS * D_MODEL];
__device__ float g_x2r [MROWS * D_MODEL];

__device__ __forceinline__ float gelu_exact(float x) {
    return 0.5f * x * (1.0f + erff(x * 0.70710678118654752f));
}

__device__ __forceinline__ float to_tf32(float x) {
    uint32_t u;
    asm volatile("cvt.rna.tf32.f32 %0, %1;" : "=r"(u) : "f"(x));
    return __uint_as_float(u);
}
__device__ __forceinline__ uint32_t to_tf32_bits(float x) {
    uint32_t u;
    asm volatile("cvt.rna.tf32.f32 %0, %1;" : "=r"(u) : "f"(x));
    return u;
}

__device__ __forceinline__ void mma_tf32(float* c, const uint32_t* a, const uint32_t* b) {
    asm volatile(
        "mma.sync.aligned.m16n8k8.row.col.f32.tf32.tf32.f32 "
        "{%0,%1,%2,%3}, {%4,%5,%6,%7}, {%8,%9}, {%0,%1,%2,%3};\n"
        : "+f"(c[0]), "+f"(c[1]), "+f"(c[2]), "+f"(c[3])
        : "r"(a[0]), "r"(a[1]), "r"(a[2]), "r"(a[3]), "r"(b[0]), "r"(b[1]));
}

// cp.async helpers
__device__ __forceinline__ void cp_async16(void* smem, const void* gmem) {
    uint32_t s = (uint32_t)__cvta_generic_to_shared(smem);
    asm volatile("cp.async.cg.shared.global [%0], [%1], 16;\n" :: "r"(s), "l"(gmem));
}
__device__ __forceinline__ void cp_commit() {
    asm volatile("cp.async.commit_group;\n" ::: "memory");
}
template<int N>
__device__ __forceinline__ void cp_wait() {
    asm volatile("cp.async.wait_group %0;\n" :: "n"(N) : "memory");
}

// ---------------------------------------------------------------------------
// Batched tf32-RNA rounding: 12 tensors in ONE launch (grid.y = tensor id)
// ---------------------------------------------------------------------------
struct RoundBatch {
    const float* src[12];
    float*       dst[12];
    int          n4[12];
};

__global__ __launch_bounds__(256)
void round_tf32_batch(RoundBatch rb)
{
    const int s = blockIdx.y;
    const float4* in  = (const float4*)rb.src[s];
    float4*       out = (float4*)rb.dst[s];
    const int n4 = rb.n4[s];
    const int stride = gridDim.x * 256;
    for (int idx = blockIdx.x * 256 + threadIdx.x; idx < n4; idx += stride) {
        float4 v = in[idx];
        v.x = to_tf32(v.x); v.y = to_tf32(v.y);
        v.z = to_tf32(v.z); v.w = to_tf32(v.w);
        out[idx] = v;
    }
}

// ---------------------------------------------------------------------------
// TF32 tensor-core GEMM: GBK=8, 4-stage cp.async, ONE barrier per k-tile.
// Inputs pre-rounded to tf32 (RNA); no cvt in the hot loop.
// C[M,N] = A[M,K] @ B[K,N] + bias, ACT 0=none 1=gelu(+tf32-rounded output)
// CTA tile 128x128, 8 warps (2x4), warp tile 64x32.
// ---------------------------------------------------------------------------
#define GBM 128
#define GBN 128
#define GBK 8
#define APAD 20
#define BPAD 136
#define STAGES 4

template<int ACT>
__global__ __launch_bounds__(256, 2)
void gemm_tf32(const float* __restrict__ A, const float* __restrict__ B,
               const float* __restrict__ bias, float* __restrict__ C,
               int M, int N, int K)
{
    __shared__ float As[STAGES][GBM][APAD];   // 40960 B
    __shared__ float Bs[STAGES][GBK][BPAD];   // 17408 B

    const int t    = threadIdx.x;
    const int wid  = t >> 5;
    const int lane = t & 31;
    const int wm   = wid >> 2;        // 0..1
    const int wn   = wid & 3;         // 0..3
    const int lr   = lane >> 2;       // 0..7
    const int lc   = lane & 3;        // 0..3

    const int m0 = blockIdx.y * GBM;
    const int n0 = blockIdx.x * GBN;

    // cp.async mapping: one 16B chunk per thread per matrix per tile
    const int arow = t >> 1;          // 0..127
    const int acol = (t & 1) * 4;     // 0 or 4
    const int brow = t >> 5;          // 0..7
    const int bcol = (t & 31) * 4;    // 0..124

    const float* Ag = A + (size_t)(m0 + arow) * K + acol;
    const float* Bg = B + (size_t)brow * N + n0 + bcol;

    float acc[4][4][4];
#pragma unroll
    for (int i = 0; i < 4; i++)
#pragma unroll
        for (int j = 0; j < 4; j++)
#pragma unroll
            for (int r = 0; r < 4; r++) acc[i][j][r] = 0.0f;

    const int kTiles = K / GBK;

    // Prologue: stages 0..2 in flight (3 groups)
#pragma unroll
    for (int s = 0; s < 3; s++) {
        const size_t ko = (size_t)s * GBK;
        cp_async16(&As[s][arow][acol], Ag + ko);
        cp_async16(&Bs[s][brow][bcol], Bg + ko * N);
        cp_commit();
    }

    int p = 0;
    for (int kt = 0; kt < kTiles; kt++) {
        cp_wait<2>();          // oldest group (tile kt) complete
        __syncthreads();       // all warps past compute of iteration kt-1

        // Issue tile kt+3 into stage (p+3)%4 (last computed at kt-1 — safe)
        if (kt + 3 < kTiles) {
            const int s = (p + 3) & 3;
            const size_t ko = (size_t)(kt + 3) * GBK;
            cp_async16(&As[s][arow][acol], Ag + ko);
            cp_async16(&Bs[s][brow][bcol], Bg + ko * N);
        }
        cp_commit();

        // ---- compute stage p (K=8) ----
        uint32_t afr[4][4];
        uint32_t bfr[4][2];
#pragma unroll
        for (int mf = 0; mf < 4; mf++) {
            const int m = wm * 64 + mf * 16 + lr;
            afr[mf][0] = __float_as_uint(As[p][m    ][lc]);
            afr[mf][1] = __float_as_uint(As[p][m + 8][lc]);
            afr[mf][2] = __float_as_uint(As[p][m    ][lc + 4]);
            afr[mf][3] = __float_as_uint(As[p][m + 8][lc + 4]);
        }
#pragma unroll
        for (int nf = 0; nf < 4; nf++) {
            const int n = wn * 32 + nf * 8 + lr;
            bfr[nf][0] = __float_as_uint(Bs[p][lc    ][n]);
            bfr[nf][1] = __float_as_uint(Bs[p][lc + 4][n]);
        }
#pragma unroll
        for (int mf = 0; mf < 4; mf++)
#pragma unroll
            for (int nf = 0; nf < 4; nf++)
                mma_tf32(acc[mf][nf], afr[mf], bfr[nf]);

        p = (p + 1) & 3;
    }

    // Epilogue
#pragma unroll
    for (int mf = 0; mf < 4; mf++) {
        const int r0 = m0 + wm * 64 + mf * 16 + lr;
#pragma unroll
        for (int nf = 0; nf < 4; nf++) {
            const int c0 = n0 + wn * 32 + nf * 8 + 2 * lc;
            const float b0 = bias[c0], b1 = bias[c0 + 1];
            float v0 = acc[mf][nf][0] + b0;
            float v1 = acc[mf][nf][1] + b1;
            float v2 = acc[mf][nf][2] + b0;
            float v3 = acc[mf][nf][3] + b1;
            if (ACT == 1) {   // gelu + round for the downstream GEMM
                v0 = to_tf32(gelu_exact(v0)); v1 = to_tf32(gelu_exact(v1));
                v2 = to_tf32(gelu_exact(v2)); v3 = to_tf32(gelu_exact(v3));
            }
            *(float2*)(C + (size_t)r0 * N + c0)       = make_float2(v0, v1);
            *(float2*)(C + (size_t)(r0 + 8) * N + c0) = make_float2(v2, v3);
        }
    }
}

// ---------------------------------------------------------------------------
// Tensor-core flash attention (TF32 mma), DK=64 — best-measured structure.
// exp in base-2: log2(e)/sqrt(dk) folded into Q; exp2f everywhere.
// Epilogue writes tf32-rounded output (sole consumer: O-proj GEMM).
// ---------------------------------------------------------------------------
#define KS_STRIDE 68
#define VS_STRIDE 72
#define QSCALE (0.125f * 1.4426950408889634f)

template<bool CAUSAL>
__global__ __launch_bounds__(256)
void flash_attn_tc(const float* __restrict__ Q, const float* __restrict__ K,
                   const float* __restrict__ V, float* __restrict__ O, int L)
{
    __shared__ float Ks[64][KS_STRIDE];
    __shared__ float Vs[64][VS_STRIDE];

    const int t    = threadIdx.x;
    const int lane = t & 31;
    const int w    = t >> 5;
    const int lr   = lane >> 2;
    const int lc   = lane & 3;

    const int qt = blockIdx.x;
    const int bh = blockIdx.y;
    const int b  = bh >> 4;
    const int h  = bh & 15;
    const int q0 = qt * 128;
    const int wrow = q0 + w * 16;

    const float* Qb = Q + (size_t)(b * L) * D_MODEL + h * DK_;
    const float* Kb = K + (size_t)(b * L) * D_MODEL + h * DK_;
    const float* Vb = V + (size_t)(b * L) * D_MODEL + h * DK_;

    uint32_t qf[8][4];
    {
        const float* qr0 = Qb + (size_t)(wrow + lr) * D_MODEL;
        const float* qr1 = Qb + (size_t)(wrow + lr + 8) * D_MODEL;
#pragma unroll
        for (int kc = 0; kc < 8; kc++) {
            qf[kc][0] = to_tf32_bits(QSCALE * qr0[8 * kc + lc]);
            qf[kc][1] = to_tf32_bits(QSCALE * qr1[8 * kc + lc]);
            qf[kc][2] = to_tf32_bits(QSCALE * qr0[8 * kc + lc + 4]);
            qf[kc][3] = to_tf32_bits(QSCALE * qr1[8 * kc + lc + 4]);
        }
    }

    float o[8][4];
#pragma unroll
    for (int nf = 0; nf < 8; nf++)
#pragma unroll
        for (int i = 0; i < 4; i++) o[nf][i] = 0.0f;
    float m0r = -1e30f, m1r = -1e30f;
    float l0r = 0.0f,  l1r = 0.0f;

    const int ntile = CAUSAL ? (2 * qt + 2) : (L >> 6);

    for (int kt = 0; kt < ntile; kt++) {
        const int k0 = kt * 64;
        __syncthreads();
#pragma unroll
        for (int i = 0; i < 4; i++) {
            const int idx = i * 256 + t;
            const int row = idx >> 4;
            const int c4  = (idx & 15) * 4;
            const size_t g = (size_t)(k0 + row) * D_MODEL + c4;
            float4 kv = *(const float4*)(Kb + g);
            float4 vv = *(const float4*)(Vb + g);
            float4 s;
            s.x = to_tf32(kv.x); s.y = to_tf32(kv.y); s.z = to_tf32(kv.z); s.w = to_tf32(kv.w);
            *(float4*)&Ks[row][c4] = s;
            s.x = to_tf32(vv.x); s.y = to_tf32(vv.y); s.z = to_tf32(vv.z); s.w = to_tf32(vv.w);
            *(float4*)&Vs[row][c4] = s;
        }
        __syncthreads();

        const bool active = (!CAUSAL) || (k0 <= wrow + 15);
        if (active) {
            float sacc[8][4];
#pragma unroll
            for (int nf = 0; nf < 8; nf++) {
                sacc[nf][0] = sacc[nf][1] = sacc[nf][2] = sacc[nf][3] = 0.0f;
#pragma unroll
                for (int kc = 0; kc < 8; kc++) {
                    uint32_t bfr[2];
                    bfr[0] = __float_as_uint(Ks[8 * nf + lr][8 * kc + lc]);
                    bfr[1] = __float_as_uint(Ks[8 * nf + lr][8 * kc + lc + 4]);
                    mma_tf32(sacc[nf], qf[kc], bfr);
                }
            }

            if (CAUSAL && (k0 + 63 > wrow)) {
                const int r0 = wrow + lr, r1 = wrow + lr + 8;
#pragma unroll
                for (int nf = 0; nf < 8; nf++) {
                    const int key = k0 + 8 * nf + 2 * lc;
                    if (key     > r0) sacc[nf][0] = -1e30f;
                    if (key + 1 > r0) sacc[nf][1] = -1e30f;
                    if (key     > r1) sacc[nf][2] = -1e30f;
                    if (key + 1 > r1) sacc[nf][3] = -1e30f;
                }
            }

            float mx0 = -1e30f, mx1 = -1e30f;
#pragma unroll
            for (int nf = 0; nf < 8; nf++) {
                mx0 = fmaxf(mx0, fmaxf(sacc[nf][0], sacc[nf][1]));
                mx1 = fmaxf(mx1, fmaxf(sacc[nf][2], sacc[nf][3]));
            }
            mx0 = fmaxf(mx0, __shfl_xor_sync(0xffffffffu, mx0, 1));
            mx0 = fmaxf(mx0, __shfl_xor_sync(0xffffffffu, mx0, 2));
            mx1 = fmaxf(mx1, __shfl_xor_sync(0xffffffffu, mx1, 1));
            mx1 = fmaxf(mx1, __shfl_xor_sync(0xffffffffu, mx1, 2));

            const float nm0 = fmaxf(m0r, mx0);
            const float nm1 = fmaxf(m1r, mx1);
            const float cr0 = exp2f(m0r - nm0);
            const float cr1 = exp2f(m1r - nm1);
            float sum0 = 0.f, sum1 = 0.f;
#pragma unroll
            for (int nf = 0; nf < 8; nf++) {
                sacc[nf][0] = exp2f(sacc[nf][0] - nm0);
                sacc[nf][1] = exp2f(sacc[nf][1] - nm0);
                sacc[nf][2] = exp2f(sacc[nf][2] - nm1);
                sacc[nf][3] = exp2f(sacc[nf][3] - nm1);
                sum0 += sacc[nf][0] + sacc[nf][1];
                sum1 += sacc[nf][2] + sacc[nf][3];
            }
            sum0 += __shfl_xor_sync(0xffffffffu, sum0, 1);
            sum0 += __shfl_xor_sync(0xffffffffu, sum0, 2);
            sum1 += __shfl_xor_sync(0xffffffffu, sum1, 1);
            sum1 += __shfl_xor_sync(0xffffffffu, sum1, 2);

            l0r = l0r * cr0 + sum0;
            l1r = l1r * cr1 + sum1;
            m0r = nm0; m1r = nm1;
#pragma unroll
            for (int nf = 0; nf < 8; nf++) {
                o[nf][0] *= cr0; o[nf][1] *= cr0;
                o[nf][2] *= cr1; o[nf][3] *= cr1;
            }

            const int qbase = lane & ~3;
            const int srcA  = qbase | (lc >> 1);
            const int srcB  = srcA + 2;
#pragma unroll
            for (int kc = 0; kc < 8; kc++) {
                const float p0a = __shfl_sync(0xffffffffu, sacc[kc][0], srcA);
                const float p1a = __shfl_sync(0xffffffffu, sacc[kc][1], srcA);
                const float p2a = __shfl_sync(0xffffffffu, sacc[kc][2], srcA);
                const float p3a = __shfl_sync(0xffffffffu, sacc[kc][3], srcA);
                const float p0b = __shfl_sync(0xffffffffu, sacc[kc][0], srcB);
                const float p1b = __shfl_sync(0xffffffffu, sacc[kc][1], srcB);
                const float p2b = __shfl_sync(0xffffffffu, sacc[kc][2], srcB);
                const float p3b = __shfl_sync(0xffffffffu, sacc[kc][3], srcB);
                uint32_t af[4];
                const bool odd = (lc & 1);
                af[0] = __float_as_uint(odd ? p1a : p0a);
                af[1] = __float_as_uint(odd ? p3a : p2a);
                af[2] = __float_as_uint(odd ? p1b : p0b);
                af[3] = __float_as_uint(odd ? p3b : p2b);
#pragma unroll
                for (int nf = 0; nf < 8; nf++) {
                    uint32_t bfr[2];
                    bfr[0] = __float_as_uint(Vs[8 * kc + lc    ][8 * nf + lr]);
                    bfr[1] = __float_as_uint(Vs[8 * kc + lc + 4][8 * nf + lr]);
                    mma_tf32(o[nf], af, bfr);
                }
            }
        }
    }

    const float inv0 = 1.0f / l0r;
    const float inv1 = 1.0f / l1r;
    float* O0 = O + (size_t)(b * L + wrow + lr) * D_MODEL + h * DK_;
    float* O1 = O + (size_t)(b * L + wrow + lr + 8) * D_MODEL + h * DK_;
#pragma unroll
    for (int nf = 0; nf < 8; nf++) {
        const int c = 8 * nf + 2 * lc;
        *(float2*)(O0 + c) = make_float2(to_tf32(o[nf][0] * inv0), to_tf32(o[nf][1] * inv0));
        *(float2*)(O1 + c) = make_float2(to_tf32(o[nf][2] * inv1), to_tf32(o[nf][3] * inv1));
    }
}

// ---------------------------------------------------------------------------
// Fused residual add + LayerNorm; DUAL also writes a tf32-rounded copy.
// ---------------------------------------------------------------------------
template<bool DUAL>
__global__ __launch_bounds__(128)
void add_layernorm(const float* __restrict__ A, const float* __restrict__ Bb,
                   const float* __restrict__ g, const float* __restrict__ be,
                   float* __restrict__ out, float* __restrict__ out_r)
{
    const int row = blockIdx.x;
    const int t = threadIdx.x;
    const float* a = A  + (size_t)row * D_MODEL;
    const float* b = Bb + (size_t)row * D_MODEL;

    float v[8];
    float s = 0.f, sq = 0.f;
#pragma unroll
    for (int i = 0; i < 8; i++) {
        const int c = t + i * 128;
        v[i] = a[c] + b[c];
        s += v[i];
        sq = fmaf(v[i], v[i], sq);
    }
#pragma unroll
    for (int o = 16; o > 0; o >>= 1) {
        s  += __shfl_down_sync(0xffffffffu, s,  o);
        sq += __shfl_down_sync(0xffffffffu, sq, o);
    }
    __shared__ float rs[4], rq[4];
    __shared__ float mean_s, rstd_s;
    const int w = t >> 5, ln = t & 31;
    if (ln == 0) { rs[w] = s; rq[w] = sq; }
    __syncthreads();
    if (t == 0) {
        const float S  = rs[0] + rs[1] + rs[2] + rs[3];
        const float Q2 = rq[0] + rq[1] + rq[2] + rq[3];
        const float mean = S * (1.0f / 1024.0f);
        const float var  = Q2 * (1.0f / 1024.0f) - mean * mean;
        mean_s = mean;
        rstd_s = rsqrtf(var + 1e-5f);
    }
    __syncthreads();
    const float mean = mean_s, rstd = rstd_s;
    float* op = out + (size_t)row * D_MODEL;
    float* orp = DUAL ? out_r + (size_t)row * D_MODEL : nullptr;
#pragma unroll
    for (int i = 0; i < 8; i++) {
        const int c = t + i * 128;
        const float y = (v[i] - mean) * rstd * g[c] + be[c];
        op[c] = y;
        if (DUAL) orp[c] = to_tf32(y);
    }
}

// ---------------------------------------------------------------------------
// Host launcher
// ---------------------------------------------------------------------------
static float* devptr(const void* sym) {
    void* p = nullptr;
    cudaGetSymbolAddress(&p, sym);
    return (float*)p;
}

extern "C" void kernel_launch(void* const* d_in, const int* in_sizes, int n_in,
                              void* d_out, int out_size)
{
    const float* x   = (const float*)d_in[0];
    const float* enc = (const float*)d_in[1];
    const float* swq = (const float*)d_in[4];
    const float* sbq = (const float*)d_in[5];
    const float* swk = (const float*)d_in[6];
    const float* sbk = (const float*)d_in[7];
    const float* swv = (const float*)d_in[8];
    const float* sbv = (const float*)d_in[9];
    const float* swo = (const float*)d_in[10];
    const float* sbo = (const float*)d_in[11];
    const float* cwq = (const float*)d_in[12];
    const float* cbq = (const float*)d_in[13];
    const float* cwk = (const float*)d_in[14];
    const float* cbk = (const float*)d_in[15];
    const float* cwv = (const float*)d_in[16];
    const float* cbv = (const float*)d_in[17];
    const float* cwo = (const float*)d_in[18];
    const float* cbo = (const float*)d_in[19];
    const float* fw1 = (const float*)d_in[20];
    const float* fb1 = (const float*)d_in[21];
    const float* fw2 = (const float*)d_in[22];
    const float* fb2 = (const float*)d_in[23];
    const float* n1g = (const float*)d_in[24];
    const float* n1b = (const float*)d_in[25];
    const float* n2g = (const float*)d_in[26];
    const float* n2b = (const float*)d_in[27];
    const float* n3g = (const float*)d_in[28];
    const float* n3b = (const float*)d_in[29];
    float* out = (float*)d_out;

    float* q    = devptr(g_q);
    float* k    = devptr(g_k);
    float* v    = devptr(g_v);
    float* ctx  = devptr(g_ctx);
    float* proj = devptr(g_proj);
    float* x1   = devptr(g_x1);
    float* x2   = devptr(g_x2);
    float* ff   = devptr(g_ff);
    float* wr   = devptr(g_wr);
    float* xr   = devptr(g_xr);
    float* er   = devptr(g_er);
    float* x1r  = devptr(g_x1r);
    float* x2r  = devptr(g_x2r);

    const int M = MROWS, Dm = D_MODEL, Dff = DFF_;
    const int W1 = Dm * Dm;
    dim3 blk(256);
    dim3 gP (Dm  / GBN, M / GBM);   // (8, 32)
    dim3 gF1(Dff / GBN, M / GBM);   // (32, 32)
    dim3 gA (SEQL / 128, 32);       // (16, B*H)

    // ---- pre-round all GEMM operands in ONE launch ----
    RoundBatch rb;
    const float* srcs[12] = {swq, swk, swv, swo, cwq, cwk, cwv, cwo,
                             fw1, fw2, x, enc};
    float* dsts[12] = {wr, wr + W1, wr + 2 * W1, wr + 3 * W1,
                       wr + 4 * W1, wr + 5 * W1, wr + 6 * W1, wr + 7 * W1,
                       wr + 8 * W1, wr + 12 * W1, xr, er};
    int n4s[12] = {W1 / 4, W1 / 4, W1 / 4, W1 / 4, W1 / 4, W1 / 4, W1 / 4, W1 / 4,
                   Dm * Dff / 4, Dff * Dm / 4, M * Dm / 4, M * Dm / 4};
    for (int i = 0; i < 12; i++) { rb.src[i] = srcs[i]; rb.dst[i] = dsts[i]; rb.n4[i] = n4s[i]; }
    round_tf32_batch<<<dim3(128, 12), 256>>>(rb);

    // ---- self attention ----
    gemm_tf32<0><<<gP, blk>>>(xr, wr + 0 * W1, sbq, q, M, Dm, Dm);
    gemm_tf32<0><<<gP, blk>>>(xr, wr + 1 * W1, sbk, k, M, Dm, Dm);
    gemm_tf32<0><<<gP, blk>>>(xr, wr + 2 * W1, sbv, v, M, Dm, Dm);
    flash_attn_tc<true><<<gA, 256>>>(q, k, v, ctx, SEQL);
    gemm_tf32<0><<<gP, blk>>>(ctx, wr + 3 * W1, sbo, proj, M, Dm, Dm);
    add_layernorm<true><<<M, 128>>>(x, proj, n1g, n1b, x1, x1r);

    // ---- cross attention ----
    gemm_tf32<0><<<gP, blk>>>(x1r, wr + 4 * W1, cbq, q, M, Dm, Dm);
    gemm_tf32<0><<<gP, blk>>>(er,  wr + 5 * W1, cbk, k, M, Dm, Dm);
    gemm_tf32<0><<<gP, blk>>>(er,  wr + 6 * W1, cbv, v, M, Dm, Dm);
    flash_attn_tc<false><<<gA, 256>>>(q, k, v, ctx, SEQL);
    gemm_tf32<0><<<gP, blk>>>(ctx, wr + 7 * W1, cbo, proj, M, Dm, Dm);
    add_layernorm<true><<<M, 128>>>(x1, proj, n2g, n2b, x2, x2r);

    // ---- feed-forward ----
    gemm_tf32<1><<<gF1, blk>>>(x2r, wr + 8 * W1,  fb1, ff, M, Dff, Dm);
    gemm_tf32<0><<<gP,  blk>>>(ff,  wr + 12 * W1, fb2, proj, M, Dm, Dff);
    add_layernorm<false><<<M, 128>>>(x2, proj, n3g, n3b, out, nullptr);
}

// round 9
// speedup vs baseline: 1.1696x; 1.0651x over previous
#include <cuda_runtime.h>
#include <math.h>
#include <stdint.h>

// Problem constants
#define D_MODEL 1024
#define NH      16
#define DK_     64
#define MROWS   4096      // B*L = 2*2048
#define DFF_    4096
#define SEQL    2048

// ---------------------------------------------------------------------------
// Scratch (static device globals; no allocations allowed)
// ---------------------------------------------------------------------------
__device__ float g_q   [MROWS * D_MODEL];
__device__ float g_k   [MROWS * D_MODEL];
__device__ float g_v   [MROWS * D_MODEL];
__device__ float g_k2  [MROWS * D_MODEL];
__device__ float g_v2  [MROWS * D_MODEL];
__device__ float g_ctx [MROWS * D_MODEL];
__device__ float g_proj[MROWS * D_MODEL];
__device__ float g_x1  [MROWS * D_MODEL];
__device__ float g_x2  [MROWS * D_MODEL];
__device__ float g_ff  [MROWS * DFF_];

__device__ __forceinline__ float gelu_exact(float x) {
    return 0.5f * x * (1.0f + erff(x * 0.70710678118654752f));
}

__device__ __forceinline__ float to_tf32(float x) {
    uint32_t u;
    asm volatile("cvt.rna.tf32.f32 %0, %1;" : "=r"(u) : "f"(x));
    return __uint_as_float(u);
}
__device__ __forceinline__ uint32_t to_tf32_bits(float x) {
    uint32_t u;
    asm volatile("cvt.rna.tf32.f32 %0, %1;" : "=r"(u) : "f"(x));
    return u;
}

__device__ __forceinline__ void mma_tf32(float* c, const uint32_t* a, const uint32_t* b) {
    asm volatile(
        "mma.sync.aligned.m16n8k8.row.col.f32.tf32.tf32.f32 "
        "{%0,%1,%2,%3}, {%4,%5,%6,%7}, {%8,%9}, {%0,%1,%2,%3};\n"
        : "+f"(c[0]), "+f"(c[1]), "+f"(c[2]), "+f"(c[3])
        : "r"(a[0]), "r"(a[1]), "r"(a[2]), "r"(a[3]), "r"(b[0]), "r"(b[1]));
}

// cp.async helpers
__device__ __forceinline__ void cp_async16(void* smem, const void* gmem) {
    uint32_t s = (uint32_t)__cvta_generic_to_shared(smem);
    asm volatile("cp.async.cg.shared.global [%0], [%1], 16;\n" :: "r"(s), "l"(gmem));
}
__device__ __forceinline__ void cp_commit() {
    asm volatile("cp.async.commit_group;\n" ::: "memory");
}
template<int N>
__device__ __forceinline__ void cp_wait() {
    asm volatile("cp.async.wait_group %0;\n" :: "n"(N) : "memory");
}

// ---------------------------------------------------------------------------
// TF32 tensor-core GEMM, cp.async 3-stage pipeline, GBK=8 (R4 — best measured)
// C[M,N] = A[M,K] @ B[K,N] + bias, ACT 0=none 1=gelu.
// ---------------------------------------------------------------------------
#define GBM 128
#define GBN 128
#define GBK 8
#define APAD 20
#define BPAD 136
#define STAGES 3

template<int ACT>
__global__ __launch_bounds__(256, 2)
void gemm_tf32(const float* __restrict__ A, const float* __restrict__ B,
               const float* __restrict__ bias, float* __restrict__ C,
               int M, int N, int K)
{
    __shared__ float As[STAGES][GBM][APAD];   // 30720 B
    __shared__ float Bs[STAGES][GBK][BPAD];   // 13056 B

    const int t    = threadIdx.x;
    const int wid  = t >> 5;
    const int lane = t & 31;
    const int wm   = wid >> 2;        // 0..1
    const int wn   = wid & 3;         // 0..3
    const int lr   = lane >> 2;       // 0..7
    const int lc   = lane & 3;        // 0..3

    const int m0 = blockIdx.y * GBM;
    const int n0 = blockIdx.x * GBN;

    const int arow = t >> 1;          // 0..127
    const int acol = (t & 1) * 4;     // 0 or 4
    const int brow = t >> 5;          // 0..7
    const int bcol = (t & 31) * 4;    // 0..124

    const float* Ag = A + (size_t)(m0 + arow) * K + acol;
    const float* Bg = B + (size_t)brow * N + n0 + bcol;

    float acc[4][4][4];
#pragma unroll
    for (int i = 0; i < 4; i++)
#pragma unroll
        for (int j = 0; j < 4; j++)
#pragma unroll
            for (int r = 0; r < 4; r++) acc[i][j][r] = 0.0f;

    const int kTiles = K / GBK;

    // Prologue: stages 0 and 1 in flight
#pragma unroll
    for (int s = 0; s < 2; s++) {
        cp_async16(&As[s][arow][acol], Ag + (size_t)s * GBK);
        cp_async16(&Bs[s][brow][bcol], Bg + (size_t)s * GBK * N);
        cp_commit();
    }

    int p = 0;
    for (int kt = 0; kt < kTiles; kt++) {
        cp_wait<1>();
        __syncthreads();

        // ---- compute stage p (K=8) ----
        uint32_t afr[4][4];
        uint32_t bfr[4][2];
#pragma unroll
        for (int mf = 0; mf < 4; mf++) {
            const int m = wm * 64 + mf * 16 + lr;
            afr[mf][0] = __float_as_uint(As[p][m    ][lc]);
            afr[mf][1] = __float_as_uint(As[p][m + 8][lc]);
            afr[mf][2] = __float_as_uint(As[p][m    ][lc + 4]);
            afr[mf][3] = __float_as_uint(As[p][m + 8][lc + 4]);
        }
#pragma unroll
        for (int nf = 0; nf < 4; nf++) {
            const int n = wn * 32 + nf * 8 + lr;
            bfr[nf][0] = __float_as_uint(Bs[p][lc    ][n]);
            bfr[nf][1] = __float_as_uint(Bs[p][lc + 4][n]);
        }
#pragma unroll
        for (int mf = 0; mf < 4; mf++)
#pragma unroll
            for (int nf = 0; nf < 4; nf++)
                mma_tf32(acc[mf][nf], afr[mf], bfr[nf]);

        // ---- issue stage kt+2 ----
        if (kt + 2 < kTiles) {
            const int s = (p + 2) % STAGES;
            const size_t ko = (size_t)(kt + 2) * GBK;
            cp_async16(&As[s][arow][acol], Ag + ko);
            cp_async16(&Bs[s][brow][bcol], Bg + ko * N);
        }
        cp_commit();

        p = (p + 1) % STAGES;
        __syncthreads();
    }

    // Epilogue
#pragma unroll
    for (int mf = 0; mf < 4; mf++) {
        const int r0 = m0 + wm * 64 + mf * 16 + lr;
#pragma unroll
        for (int nf = 0; nf < 4; nf++) {
            const int c0 = n0 + wn * 32 + nf * 8 + 2 * lc;
            const float b0 = bias[c0], b1 = bias[c0 + 1];
            float v0 = acc[mf][nf][0] + b0;
            float v1 = acc[mf][nf][1] + b1;
            float v2 = acc[mf][nf][2] + b0;
            float v3 = acc[mf][nf][3] + b1;
            if (ACT == 1) {
                v0 = gelu_exact(v0); v1 = gelu_exact(v1);
                v2 = gelu_exact(v2); v3 = gelu_exact(v3);
            }
            *(float2*)(C + (size_t)r0 * N + c0)       = make_float2(v0, v1);
            *(float2*)(C + (size_t)(r0 + 8) * N + c0) = make_float2(v2, v3);
        }
    }
}

// ---------------------------------------------------------------------------
// Tensor-core flash attention (TF32 mma), DK=64 — R3/R4 structure (measured best)
// ---------------------------------------------------------------------------
#define KS_STRIDE 68
#define VS_STRIDE 72

template<bool CAUSAL>
__global__ __launch_bounds__(256)
void flash_attn_tc(const float* __restrict__ Q, const float* __restrict__ K,
                   const float* __restrict__ V, float* __restrict__ O, int L)
{
    __shared__ float Ks[64][KS_STRIDE];
    __shared__ float Vs[64][VS_STRIDE];

    const int t    = threadIdx.x;
    const int lane = t & 31;
    const int w    = t >> 5;
    const int lr   = lane >> 2;
    const int lc   = lane & 3;

    const int qt = blockIdx.x;
    const int bh = blockIdx.y;
    const int b  = bh >> 4;
    const int h  = bh & 15;
    const int q0 = qt * 128;
    const int wrow = q0 + w * 16;

    const float* Qb = Q + (size_t)(b * L) * D_MODEL + h * DK_;
    const float* Kb = K + (size_t)(b * L) * D_MODEL + h * DK_;
    const float* Vb = V + (size_t)(b * L) * D_MODEL + h * DK_;

    uint32_t qf[8][4];
    {
        const float* qr0 = Qb + (size_t)(wrow + lr) * D_MODEL;
        const float* qr1 = Qb + (size_t)(wrow + lr + 8) * D_MODEL;
#pragma unroll
        for (int kc = 0; kc < 8; kc++) {
            qf[kc][0] = to_tf32_bits(0.125f * qr0[8 * kc + lc]);
            qf[kc][1] = to_tf32_bits(0.125f * qr1[8 * kc + lc]);
            qf[kc][2] = to_tf32_bits(0.125f * qr0[8 * kc + lc + 4]);
            qf[kc][3] = to_tf32_bits(0.125f * qr1[8 * kc + lc + 4]);
        }
    }

    float o[8][4];
#pragma unroll
    for (int nf = 0; nf < 8; nf++)
#pragma unroll
        for (int i = 0; i < 4; i++) o[nf][i] = 0.0f;
    float m0r = -1e30f, m1r = -1e30f;
    float l0r = 0.0f,  l1r = 0.0f;

    const int ntile = CAUSAL ? (2 * qt + 2) : (L >> 6);

    for (int kt = 0; kt < ntile; kt++) {
        const int k0 = kt * 64;
        __syncthreads();
#pragma unroll
        for (int i = 0; i < 4; i++) {
            const int idx = i * 256 + t;
            const int row = idx >> 4;
            const int c4  = (idx & 15) * 4;
            const size_t g = (size_t)(k0 + row) * D_MODEL + c4;
            float4 kv = *(const float4*)(Kb + g);
            float4 vv = *(const float4*)(Vb + g);
            float4 s;
            s.x = to_tf32(kv.x); s.y = to_tf32(kv.y); s.z = to_tf32(kv.z); s.w = to_tf32(kv.w);
            *(float4*)&Ks[row][c4] = s;
            s.x = to_tf32(vv.x); s.y = to_tf32(vv.y); s.z = to_tf32(vv.z); s.w = to_tf32(vv.w);
            *(float4*)&Vs[row][c4] = s;
        }
        __syncthreads();

        const bool active = (!CAUSAL) || (k0 <= wrow + 15);
        if (active) {
            float sacc[8][4];
#pragma unroll
            for (int nf = 0; nf < 8; nf++) {
                sacc[nf][0] = sacc[nf][1] = sacc[nf][2] = sacc[nf][3] = 0.0f;
#pragma unroll
                for (int kc = 0; kc < 8; kc++) {
                    uint32_t bfr[2];
                    bfr[0] = __float_as_uint(Ks[8 * nf + lr][8 * kc + lc]);
                    bfr[1] = __float_as_uint(Ks[8 * nf + lr][8 * kc + lc + 4]);
                    mma_tf32(sacc[nf], qf[kc], bfr);
                }
            }

            if (CAUSAL && (k0 + 63 > wrow)) {
                const int r0 = wrow + lr, r1 = wrow + lr + 8;
#pragma unroll
                for (int nf = 0; nf < 8; nf++) {
                    const int key = k0 + 8 * nf + 2 * lc;
                    if (key     > r0) sacc[nf][0] = -1e30f;
                    if (key + 1 > r0) sacc[nf][1] = -1e30f;
                    if (key     > r1) sacc[nf][2] = -1e30f;
                    if (key + 1 > r1) sacc[nf][3] = -1e30f;
                }
            }

            float mx0 = -1e30f, mx1 = -1e30f;
#pragma unroll
            for (int nf = 0; nf < 8; nf++) {
                mx0 = fmaxf(mx0, fmaxf(sacc[nf][0], sacc[nf][1]));
                mx1 = fmaxf(mx1, fmaxf(sacc[nf][2], sacc[nf][3]));
            }
            mx0 = fmaxf(mx0, __shfl_xor_sync(0xffffffffu, mx0, 1));
            mx0 = fmaxf(mx0, __shfl_xor_sync(0xffffffffu, mx0, 2));
            mx1 = fmaxf(mx1, __shfl_xor_sync(0xffffffffu, mx1, 1));
            mx1 = fmaxf(mx1, __shfl_xor_sync(0xffffffffu, mx1, 2));

            const float nm0 = fmaxf(m0r, mx0);
            const float nm1 = fmaxf(m1r, mx1);
            const float cr0 = __expf(m0r - nm0);
            const float cr1 = __expf(m1r - nm1);
            float sum0 = 0.f, sum1 = 0.f;
#pragma unroll
            for (int nf = 0; nf < 8; nf++) {
                sacc[nf][0] = __expf(sacc[nf][0] - nm0);
                sacc[nf][1] = __expf(sacc[nf][1] - nm0);
                sacc[nf][2] = __expf(sacc[nf][2] - nm1);
                sacc[nf][3] = __expf(sacc[nf][3] - nm1);
                sum0 += sacc[nf][0] + sacc[nf][1];
                sum1 += sacc[nf][2] + sacc[nf][3];
            }
            sum0 += __shfl_xor_sync(0xffffffffu, sum0, 1);
            sum0 += __shfl_xor_sync(0xffffffffu, sum0, 2);
            sum1 += __shfl_xor_sync(0xffffffffu, sum1, 1);
            sum1 += __shfl_xor_sync(0xffffffffu, sum1, 2);

            l0r = l0r * cr0 + sum0;
            l1r = l1r * cr1 + sum1;
            m0r = nm0; m1r = nm1;
#pragma unroll
            for (int nf = 0; nf < 8; nf++) {
                o[nf][0] *= cr0; o[nf][1] *= cr0;
                o[nf][2] *= cr1; o[nf][3] *= cr1;
            }

            const int qbase = lane & ~3;
            const int srcA  = qbase | (lc >> 1);
            const int srcB  = srcA + 2;
#pragma unroll
            for (int kc = 0; kc < 8; kc++) {
                const float p0a = __shfl_sync(0xffffffffu, sacc[kc][0], srcA);
                const float p1a = __shfl_sync(0xffffffffu, sacc[kc][1], srcA);
                const float p2a = __shfl_sync(0xffffffffu, sacc[kc][2], srcA);
                const float p3a = __shfl_sync(0xffffffffu, sacc[kc][3], srcA);
                const float p0b = __shfl_sync(0xffffffffu, sacc[kc][0], srcB);
                const float p1b = __shfl_sync(0xffffffffu, sacc[kc][1], srcB);
                const float p2b = __shfl_sync(0xffffffffu, sacc[kc][2], srcB);
                const float p3b = __shfl_sync(0xffffffffu, sacc[kc][3], srcB);
                uint32_t af[4];
                const bool odd = (lc & 1);
                af[0] = __float_as_uint(odd ? p1a : p0a);
                af[1] = __float_as_uint(odd ? p3a : p2a);
                af[2] = __float_as_uint(odd ? p1b : p0b);
                af[3] = __float_as_uint(odd ? p3b : p2b);
#pragma unroll
                for (int nf = 0; nf < 8; nf++) {
                    uint32_t bfr[2];
                    bfr[0] = __float_as_uint(Vs[8 * kc + lc    ][8 * nf + lr]);
                    bfr[1] = __float_as_uint(Vs[8 * kc + lc + 4][8 * nf + lr]);
                    mma_tf32(o[nf], af, bfr);
                }
            }
        }
    }

    const float inv0 = 1.0f / l0r;
    const float inv1 = 1.0f / l1r;
    float* O0 = O + (size_t)(b * L + wrow + lr) * D_MODEL + h * DK_;
    float* O1 = O + (size_t)(b * L + wrow + lr + 8) * D_MODEL + h * DK_;
#pragma unroll
    for (int nf = 0; nf < 8; nf++) {
        const int c = 8 * nf + 2 * lc;
        *(float2*)(O0 + c) = make_float2(o[nf][0] * inv0, o[nf][1] * inv0);
        *(float2*)(O1 + c) = make_float2(o[nf][2] * inv1, o[nf][3] * inv1);
    }
}

// ---------------------------------------------------------------------------
// Fused residual add + LayerNorm over last dim (1024). 1 block / row.
// ---------------------------------------------------------------------------
__global__ __launch_bounds__(128)
void add_layernorm(const float* __restrict__ A, const float* __restrict__ Bb,
                   const float* __restrict__ g, const float* __restrict__ be,
                   float* __restrict__ out)
{
    const int row = blockIdx.x;
    const int t = threadIdx.x;
    const float* a = A  + (size_t)row * D_MODEL;
    const float* b = Bb + (size_t)row * D_MODEL;

    float v[8];
    float s = 0.f, sq = 0.f;
#pragma unroll
    for (int i = 0; i < 8; i++) {
        const int c = t + i * 128;
        v[i] = a[c] + b[c];
        s += v[i];
        sq = fmaf(v[i], v[i], sq);
    }
#pragma unroll
    for (int o = 16; o > 0; o >>= 1) {
        s  += __shfl_down_sync(0xffffffffu, s,  o);
        sq += __shfl_down_sync(0xffffffffu, sq, o);
    }
    __shared__ float rs[4], rq[4];
    __shared__ float mean_s, rstd_s;
    const int w = t >> 5, ln = t & 31;
    if (ln == 0) { rs[w] = s; rq[w] = sq; }
    __syncthreads();
    if (t == 0) {
        const float S  = rs[0] + rs[1] + rs[2] + rs[3];
        const float Q2 = rq[0] + rq[1] + rq[2] + rq[3];
        const float mean = S * (1.0f / 1024.0f);
        const float var  = Q2 * (1.0f / 1024.0f) - mean * mean;
        mean_s = mean;
        rstd_s = rsqrtf(var + 1e-5f);
    }
    __syncthreads();
    const float mean = mean_s, rstd = rstd_s;
    float* op = out + (size_t)row * D_MODEL;
#pragma unroll
    for (int i = 0; i < 8; i++) {
        const int c = t + i * 128;
        op[c] = (v[i] - mean) * rstd * g[c] + be[c];
    }
}

// ---------------------------------------------------------------------------
// Host launcher — fork/join side stream overlaps cross K/V projections
// (enc-dependent only) with the entire self-attention block.
// ---------------------------------------------------------------------------
static float* devptr(const void* sym) {
    void* p = nullptr;
    cudaGetSymbolAddress(&p, sym);
    return (float*)p;
}

extern "C" void kernel_launch(void* const* d_in, const int* in_sizes, int n_in,
                              void* d_out, int out_size)
{
    const float* x   = (const float*)d_in[0];
    const float* enc = (const float*)d_in[1];
    const float* swq = (const float*)d_in[4];
    const float* sbq = (const float*)d_in[5];
    const float* swk = (const float*)d_in[6];
    const float* sbk = (const float*)d_in[7];
    const float* swv = (const float*)d_in[8];
    const float* sbv = (const float*)d_in[9];
    const float* swo = (const float*)d_in[10];
    const float* sbo = (const float*)d_in[11];
    const float* cwq = (const float*)d_in[12];
    const float* cbq = (const float*)d_in[13];
    const float* cwk = (const float*)d_in[14];
    const float* cbk = (const float*)d_in[15];
    const float* cwv = (const float*)d_in[16];
    const float* cbv = (const float*)d_in[17];
    const float* cwo = (const float*)d_in[18];
    const float* cbo = (const float*)d_in[19];
    const float* fw1 = (const float*)d_in[20];
    const float* fb1 = (const float*)d_in[21];
    const float* fw2 = (const float*)d_in[22];
    const float* fb2 = (const float*)d_in[23];
    const float* n1g = (const float*)d_in[24];
    const float* n1b = (const float*)d_in[25];
    const float* n2g = (const float*)d_in[26];
    const float* n2b = (const float*)d_in[27];
    const float* n3g = (const float*)d_in[28];
    const float* n3b = (const float*)d_in[29];
    float* out = (float*)d_out;

    float* q    = devptr(g_q);
    float* k    = devptr(g_k);
    float* v    = devptr(g_v);
    float* k2   = devptr(g_k2);
    float* v2   = devptr(g_v2);
    float* ctx  = devptr(g_ctx);
    float* proj = devptr(g_proj);
    float* x1   = devptr(g_x1);
    float* x2   = devptr(g_x2);
    float* ff   = devptr(g_ff);

    // Lazily create side stream + fork/join events on the FIRST (uncaptured)
    // call; reused identically on the capture call. Fallback: serialize on
    // the main stream if creation fails.
    static cudaStream_t s2 = nullptr;
    static cudaEvent_t evFork = nullptr, evJoin = nullptr;
    static bool tried = false;
    if (!tried) {
        tried = true;
        if (cudaStreamCreateWithFlags(&s2, cudaStreamNonBlocking) != cudaSuccess) s2 = nullptr;
        if (s2) {
            if (cudaEventCreateWithFlags(&evFork, cudaEventDisableTiming) != cudaSuccess ||
                cudaEventCreateWithFlags(&evJoin, cudaEventDisableTiming) != cudaSuccess) {
                s2 = nullptr;
            }
        }
    }
    const bool dual = (s2 != nullptr);
    cudaStream_t sideStream = dual ? s2 : (cudaStream_t)0;

    const int M = MROWS, Dm = D_MODEL, Dff = DFF_;
    dim3 blk(256);
    dim3 gP (Dm  / GBN, M / GBM);   // (8, 32)
    dim3 gF1(Dff / GBN, M / GBM);   // (32, 32)
    dim3 gA (SEQL / 128, 32);       // (16, B*H)

    // ---- fork: cross K/V projections (depend only on enc) on side stream ----
    if (dual) {
        cudaEventRecord(evFork, 0);
        cudaStreamWaitEvent(s2, evFork, 0);
    }
    gemm_tf32<0><<<gP, blk, 0, sideStream>>>(enc, cwk, cbk, k2, M, Dm, Dm);
    gemm_tf32<0><<<gP, blk, 0, sideStream>>>(enc, cwv, cbv, v2, M, Dm, Dm);
    if (dual) cudaEventRecord(evJoin, s2);

    // ---- self attention (main stream) ----
    gemm_tf32<0><<<gP, blk>>>(x, swq, sbq, q, M, Dm, Dm);
    gemm_tf32<0><<<gP, blk>>>(x, swk, sbk, k, M, Dm, Dm);
    gemm_tf32<0><<<gP, blk>>>(x, swv, sbv, v, M, Dm, Dm);
    flash_attn_tc<true><<<gA, 256>>>(q, k, v, ctx, SEQL);
    gemm_tf32<0><<<gP, blk>>>(ctx, swo, sbo, proj, M, Dm, Dm);
    add_layernorm<<<M, 128>>>(x, proj, n1g, n1b, x1);

    // ---- cross attention ----
    gemm_tf32<0><<<gP, blk>>>(x1, cwq, cbq, q, M, Dm, Dm);
    if (dual) cudaStreamWaitEvent((cudaStream_t)0, evJoin, 0);   // join k2/v2
    flash_attn_tc<false><<<gA, 256>>>(q, k2, v2, ctx, SEQL);
    gemm_tf32<0><<<gP, blk>>>(ctx, cwo, cbo, proj, M, Dm, Dm);
    add_layernorm<<<M, 128>>>(x1, proj, n2g, n2b, x2);

    // ---- feed-forward ----
    gemm_tf32<1><<<gF1, blk>>>(x2, fw1, fb1, ff, M, Dff, Dm);
    gemm_tf32<0><<<gP,  blk>>>(ff, fw2, fb2, proj, M, Dm, Dff);
    add_layernorm<<<M, 128>>>(x2, proj, n3g, n3b, out);
}